// round 15
// baseline (speedup 1.0000x reference)
#include <cuda_runtime.h>

#define NRAYS 65536
#define NPTS 32
#define FEATD 128
#define DIM 512
#define NLAYERS 6
#define K0 4096   /* NPTS * FEATD */

#define BM 128
#define BN 128
#define BK 8

// Scratch (allocation-free rule: __device__ globals)
__device__ float g_X[(size_t)NRAYS * K0];    // 1 GiB interp features
__device__ float g_h[(size_t)NRAYS * DIM];   // GEMM output
__device__ float g_y[(size_t)NRAYS * DIM];   // relu+LN output
__device__ float g_len[NRAYS];
__device__ unsigned char g_mask[NRAYS];      // normalized mask
__device__ int g_mask_kind;                  // 0=u8, 1=i32, 2=f32

// ---------- packed f32x2 helpers (FFMA2 path, 2x fp32 issue rate) ----------
static __device__ __forceinline__ unsigned long long pk2(float x, float y) {
    unsigned long long r;
    asm("mov.b64 %0, {%1, %2};" : "=l"(r) : "f"(x), "f"(y));
    return r;
}
static __device__ __forceinline__ unsigned long long ff2(unsigned long long a,
                                                         unsigned long long b,
                                                         unsigned long long c) {
    unsigned long long d;
    asm("fma.rn.f32x2 %0, %1, %2, %3;" : "=l"(d) : "l"(a), "l"(b), "l"(c));
    return d;
}
static __device__ __forceinline__ void upk2(unsigned long long v, float& x, float& y) {
    asm("mov.b64 {%0, %1}, %2;" : "=f"(x), "=f"(y) : "l"(v));
}

// ---------------------------------------------------------------------------
// Mask dtype detection + normalization (deterministic). u8 bools: ~90% of
// bytes == 1. int32 0/1: ~22.5% of bytes == 1. float32 1.0f: ~0%.
// ---------------------------------------------------------------------------
__global__ void detect_mask_kernel(const unsigned char* __restrict__ mraw)
{
    int c1 = 0;
    for (int i = 0; i < 512; i++) c1 += (mraw[i] == 1);
    int kind;
    if (c1 > 256)     kind = 0;   // u8
    else if (c1 > 25) kind = 1;   // i32
    else              kind = 2;   // f32
    g_mask_kind = kind;
}

__global__ void norm_mask_kernel(const unsigned char* __restrict__ mraw)
{
    int r = blockIdx.x * blockDim.x + threadIdx.x;
    if (r >= NRAYS) return;
    int kind = g_mask_kind;
    bool m;
    if (kind == 0)      m = (mraw[r] != 0);
    else if (kind == 1) m = (((const int*)mraw)[r] != 0);
    else                m = (((const float*)mraw)[r] != 0.0f);
    g_mask[r] = m ? 1 : 0;
}

// ---------------------------------------------------------------------------
// Kernel 1: per-ray trilinear interpolation -> g_X [NRAYS, 4096], g_len
// One warp per ray; each lane owns 4 consecutive features (float4).
// ---------------------------------------------------------------------------
__global__ void feature_kernel(const float* __restrict__ orig,
                               const float* __restrict__ vec,
                               const float* __restrict__ t1g,
                               const float* __restrict__ t2g,
                               const float* __restrict__ nming,
                               const float* __restrict__ nmaxg,
                               const float* __restrict__ feats,
                               const int*   __restrict__ idxs)
{
    int r = (blockIdx.x * blockDim.x + threadIdx.x) >> 5;
    int lane = threadIdx.x & 31;
    if (r >= NRAYS) return;

    int idx = g_mask[r] ? idxs[r] : 0;
    float a1 = t1g[r], a2 = t2g[r];
    float ox = orig[3*r+0], oy = orig[3*r+1], oz = orig[3*r+2];
    float vx = vec[3*r+0],  vy = vec[3*r+1],  vz = vec[3*r+2];

    float iox = fmaf(vx, a1, ox), ioy = fmaf(vy, a1, oy), ioz = fmaf(vz, a1, oz);
    float dt  = a2 - a1;
    float ivx = vx * dt, ivy = vy * dt, ivz = vz * dt;
    float iex = iox + ivx, iey = ioy + ivy, iez = ioz + ivz;

    float nx = nming[3*idx+0], ny = nming[3*idx+1], nz = nming[3*idx+2];
    float sx = nmaxg[3*idx+0] - nx;
    float sy = nmaxg[3*idx+1] - ny;
    float sz = nmaxg[3*idx+2] - nz;

    float o0 = fminf(fmaxf((iox - nx) / sx, 0.f), 1.f);
    float o1 = fminf(fmaxf((ioy - ny) / sy, 0.f), 1.f);
    float o2 = fminf(fmaxf((ioz - nz) / sz, 0.f), 1.f);
    float e0 = fminf(fmaxf((iex - nx) / sx, 0.f), 1.f);
    float e1 = fminf(fmaxf((iey - ny) / sy, 0.f), 1.f);
    float e2 = fminf(fmaxf((iez - nz) / sz, 0.f), 1.f);

    if (lane == 0)
        g_len[r] = sqrtf(ivx*ivx + ivy*ivy + ivz*ivz);

    // 8 corner feature vectors, this lane's float4 slice of each
    const float4* fb = (const float4*)(feats + (size_t)idx * 1024);
    float4 f0 = fb[  0 + lane], f1 = fb[ 32 + lane], f2 = fb[ 64 + lane], f3 = fb[ 96 + lane];
    float4 f4 = fb[128 + lane], f5 = fb[160 + lane], f6 = fb[192 + lane], f7 = fb[224 + lane];

    float4* Xo = (float4*)(g_X + (size_t)r * K0) + lane;
    float d0 = e0 - o0, d1 = e1 - o1, d2 = e2 - o2;

    #pragma unroll 4
    for (int p = 0; p < NPTS; p++) {
        float t = (float)p * (1.0f / 31.0f);
        float x = fmaf(d0, t, o0), y = fmaf(d1, t, o1), z = fmaf(d2, t, o2);
        float mx = 1.f - x, my = 1.f - y, mz = 1.f - z;
        float w0 = mx*my*mz, w1 = x*my*mz, w2 = mx*y*mz, w3 = mx*my*z;
        float w4 = x*my*z,  w5 = mx*y*z,  w6 = x*y*mz,  w7 = x*y*z;
        float4 o4;
        o4.x = w0*f0.x; o4.y = w0*f0.y; o4.z = w0*f0.z; o4.w = w0*f0.w;
        o4.x = fmaf(w1,f1.x,o4.x); o4.y = fmaf(w1,f1.y,o4.y); o4.z = fmaf(w1,f1.z,o4.z); o4.w = fmaf(w1,f1.w,o4.w);
        o4.x = fmaf(w2,f2.x,o4.x); o4.y = fmaf(w2,f2.y,o4.y); o4.z = fmaf(w2,f2.z,o4.z); o4.w = fmaf(w2,f2.w,o4.w);
        o4.x = fmaf(w3,f3.x,o4.x); o4.y = fmaf(w3,f3.y,o4.y); o4.z = fmaf(w3,f3.z,o4.z); o4.w = fmaf(w3,f3.w,o4.w);
        o4.x = fmaf(w4,f4.x,o4.x); o4.y = fmaf(w4,f4.y,o4.y); o4.z = fmaf(w4,f4.z,o4.z); o4.w = fmaf(w4,f4.w,o4.w);
        o4.x = fmaf(w5,f5.x,o4.x); o4.y = fmaf(w5,f5.y,o4.y); o4.z = fmaf(w5,f5.z,o4.z); o4.w = fmaf(w5,f5.w,o4.w);
        o4.x = fmaf(w6,f6.x,o4.x); o4.y = fmaf(w6,f6.y,o4.y); o4.z = fmaf(w6,f6.z,o4.z); o4.w = fmaf(w6,f6.w,o4.w);
        o4.x = fmaf(w7,f7.x,o4.x); o4.y = fmaf(w7,f7.y,o4.y); o4.z = fmaf(w7,f7.z,o4.z); o4.w = fmaf(w7,f7.w,o4.w);
        Xo[p * 32] = o4;
    }
}

// ---------------------------------------------------------------------------
// Kernel 2: C[M,512] = A[M,K] * B^T + bias, fp32 via packed FFMA2.
// mode 0: A=g_X, K=4096 (layer 0).  mode 1: A=g_y, K=512 (hidden layers).
// Double-buffered smem, 128x128x8 tile, 8x8 per thread, 256 threads.
// ---------------------------------------------------------------------------
__global__ __launch_bounds__(256, 2)
void gemm_kernel(int mode, const float* __restrict__ B, const float* __restrict__ bias)
{
    const int K = mode ? DIM : K0;
    const float* __restrict__ A = mode ? g_y : g_X;
    float* __restrict__ C = g_h;

    __shared__ __align__(16) float As[2][BK][BM];
    __shared__ __align__(16) float Bs[2][BK][BN];

    const int tid = threadIdx.x;
    const int bm = blockIdx.y * BM;
    const int bn = blockIdx.x * BN;

    const float* Ap = A + (size_t)(bm + (tid >> 1)) * K + (tid & 1) * 4;
    const float* Bp = B + (size_t)(bn + (tid >> 1)) * K + (tid & 1) * 4;
    const int srow = (tid & 1) * 4;
    const int scol = tid >> 1;

    // prologue: tile 0 -> buffer 0
    {
        float4 av = *(const float4*)Ap;
        float4 bv = *(const float4*)Bp;
        As[0][srow+0][scol] = av.x; As[0][srow+1][scol] = av.y;
        As[0][srow+2][scol] = av.z; As[0][srow+3][scol] = av.w;
        Bs[0][srow+0][scol] = bv.x; Bs[0][srow+1][scol] = bv.y;
        Bs[0][srow+2][scol] = bv.z; Bs[0][srow+3][scol] = bv.w;
    }
    __syncthreads();

    const int tx = tid & 15;       // col group (8 cols)
    const int ty = tid >> 4;       // row group (8 rows)

    unsigned long long acc[8][4];
    #pragma unroll
    for (int i = 0; i < 8; i++)
        #pragma unroll
        for (int j = 0; j < 4; j++)
            acc[i][j] = 0ull;

    const int ktiles = K / BK;
    int buf = 0;
    for (int kt = 0; kt < ktiles; kt++) {
        float4 an, bnv;
        const bool pf = (kt + 1 < ktiles);
        if (pf) {
            an  = *(const float4*)(Ap + (kt + 1) * BK);
            bnv = *(const float4*)(Bp + (kt + 1) * BK);
        }
        float (*Ac)[BM] = As[buf];
        float (*Bc)[BN] = Bs[buf];
        #pragma unroll
        for (int kk = 0; kk < BK; kk++) {
            float4 a0 = *(const float4*)&Ac[kk][ty * 8];
            float4 a1 = *(const float4*)&Ac[kk][ty * 8 + 4];
            const unsigned long long* bp = (const unsigned long long*)&Bc[kk][tx * 8];
            unsigned long long b0 = bp[0], b1 = bp[1], b2 = bp[2], b3 = bp[3];
            float a[8] = {a0.x, a0.y, a0.z, a0.w, a1.x, a1.y, a1.z, a1.w};
            #pragma unroll
            for (int i = 0; i < 8; i++) {
                unsigned long long aa = pk2(a[i], a[i]);
                acc[i][0] = ff2(aa, b0, acc[i][0]);
                acc[i][1] = ff2(aa, b1, acc[i][1]);
                acc[i][2] = ff2(aa, b2, acc[i][2]);
                acc[i][3] = ff2(aa, b3, acc[i][3]);
            }
        }
        if (pf) {
            float (*An_)[BM] = As[buf ^ 1];
            float (*Bn_)[BN] = Bs[buf ^ 1];
            An_[srow+0][scol] = an.x;  An_[srow+1][scol] = an.y;
            An_[srow+2][scol] = an.z;  An_[srow+3][scol] = an.w;
            Bn_[srow+0][scol] = bnv.x; Bn_[srow+1][scol] = bnv.y;
            Bn_[srow+2][scol] = bnv.z; Bn_[srow+3][scol] = bnv.w;
        }
        __syncthreads();
        buf ^= 1;
    }

    // epilogue: bias add + store
    float4 bb0 = *(const float4*)(bias + bn + tx * 8);
    float4 bb1 = *(const float4*)(bias + bn + tx * 8 + 4);
    #pragma unroll
    for (int i = 0; i < 8; i++) {
        float o0, o1, o2, o3, o4, o5, o6, o7;
        upk2(acc[i][0], o0, o1);
        upk2(acc[i][1], o2, o3);
        upk2(acc[i][2], o4, o5);
        upk2(acc[i][3], o6, o7);
        float4 r0 = make_float4(o0 + bb0.x, o1 + bb0.y, o2 + bb0.z, o3 + bb0.w);
        float4 r1 = make_float4(o4 + bb1.x, o5 + bb1.y, o6 + bb1.z, o7 + bb1.w);
        float* crow = C + (size_t)(bm + ty * 8 + i) * DIM + bn + tx * 8;
        *(float4*)crow       = r0;
        *(float4*)(crow + 4) = r1;
    }
}

// ---------------------------------------------------------------------------
// Kernel 3: y = gamma * LN(relu(h)) + beta     (warp per row)
// ---------------------------------------------------------------------------
__global__ void prep_kernel(const float* __restrict__ gamma, const float* __restrict__ beta)
{
    int r = (blockIdx.x * blockDim.x + threadIdx.x) >> 5;
    int lane = threadIdx.x & 31;
    if (r >= NRAYS) return;

    const float4* hp = (const float4*)(g_h + (size_t)r * DIM);
    float4 v[4];
    float s = 0.f, s2 = 0.f;
    #pragma unroll
    for (int q = 0; q < 4; q++) {
        float4 t = hp[q * 32 + lane];
        t.x = fmaxf(t.x, 0.f); t.y = fmaxf(t.y, 0.f);
        t.z = fmaxf(t.z, 0.f); t.w = fmaxf(t.w, 0.f);
        v[q] = t;
        s  += t.x + t.y + t.z + t.w;
        s2 += t.x*t.x + t.y*t.y + t.z*t.z + t.w*t.w;
    }
    #pragma unroll
    for (int o = 16; o; o >>= 1) {
        s  += __shfl_xor_sync(0xffffffffu, s,  o);
        s2 += __shfl_xor_sync(0xffffffffu, s2, o);
    }
    float mu   = s * (1.0f / DIM);
    float var  = fmaf(-mu, mu, s2 * (1.0f / DIM));
    float rstd = rsqrtf(var + 1e-5f);

    float4* yp = (float4*)(g_y + (size_t)r * DIM);
    #pragma unroll
    for (int q = 0; q < 4; q++) {
        int c0 = q * 128 + lane * 4;
        float4 g4 = *(const float4*)(gamma + c0);
        float4 b4 = *(const float4*)(beta + c0);
        float4 o4;
        o4.x = fmaf((v[q].x - mu) * rstd, g4.x, b4.x);
        o4.y = fmaf((v[q].y - mu) * rstd, g4.y, b4.y);
        o4.z = fmaf((v[q].z - mu) * rstd, g4.z, b4.z);
        o4.w = fmaf((v[q].w - mu) * rstd, g4.w, b4.w);
        yp[q * 32 + lane] = o4;
    }
}

// ---------------------------------------------------------------------------
// Kernel 4: heads + mask logic -> out[2, NRAYS]
// ---------------------------------------------------------------------------
__global__ void head_kernel(const float* __restrict__ Wcls, const float* __restrict__ bcls,
                            const float* __restrict__ Wdist, const float* __restrict__ bdist,
                            const float* __restrict__ t1g, const float* __restrict__ din,
                            float* __restrict__ out)
{
    int r = (blockIdx.x * blockDim.x + threadIdx.x) >> 5;
    int lane = threadIdx.x & 31;
    if (r >= NRAYS) return;

    const float4* hp = (const float4*)(g_h + (size_t)r * DIM);
    float sc = 0.f, sd = 0.f;
    #pragma unroll
    for (int q = 0; q < 4; q++) {
        float4 hv = hp[q * 32 + lane];
        hv.x = fmaxf(hv.x, 0.f); hv.y = fmaxf(hv.y, 0.f);
        hv.z = fmaxf(hv.z, 0.f); hv.w = fmaxf(hv.w, 0.f);
        int c0 = q * 128 + lane * 4;
        float4 wc = *(const float4*)(Wcls + c0);
        float4 wd = *(const float4*)(Wdist + c0);
        sc += hv.x*wc.x + hv.y*wc.y + hv.z*wc.z + hv.w*wc.w;
        sd += hv.x*wd.x + hv.y*wd.y + hv.z*wd.z + hv.w*wd.w;
    }
    #pragma unroll
    for (int o = 16; o; o >>= 1) {
        sc += __shfl_xor_sync(0xffffffffu, sc, o);
        sd += __shfl_xor_sync(0xffffffffu, sd, o);
    }
    if (lane == 0) {
        float cls  = sc + bcls[0];
        float dist = (sd + bdist[0]) * g_len[r];
        bool  m    = (g_mask[r] != 0);
        float hit  = m ? cls : 0.f;
        float dval = (m ? dist : 0.f) + t1g[r];
        float di   = din[r];
        bool  upd  = (hit > 0.f) && (dval < di) && m;
        out[r]         = hit;
        out[NRAYS + r] = upd ? dval : di;
    }
}

// ---------------------------------------------------------------------------
extern "C" void kernel_launch(void* const* d_in, const int* in_sizes, int n_in,
                              void* d_out, int out_size)
{
    const float* orig   = (const float*)d_in[0];
    const float* vec    = (const float*)d_in[1];
    const float* t1     = (const float*)d_in[2];
    const float* t2     = (const float*)d_in[3];
    const float* din    = (const float*)d_in[4];
    const float* nmin   = (const float*)d_in[5];
    const float* nmax   = (const float*)d_in[6];
    const float* feats  = (const float*)d_in[7];
    const float* W0     = (const float*)d_in[8];
    const float* b0     = (const float*)d_in[9];
    const float* Wl     = (const float*)d_in[10];
    const float* bl     = (const float*)d_in[11];
    const float* gl     = (const float*)d_in[12];
    const float* betal  = (const float*)d_in[13];
    const float* Wcls   = (const float*)d_in[14];
    const float* bcls   = (const float*)d_in[15];
    const float* Wdist  = (const float*)d_in[16];
    const float* bdist  = (const float*)d_in[17];
    const int*   idxs   = (const int*)d_in[18];
    const unsigned char* mraw = (const unsigned char*)d_in[19];
    float* out = (float*)d_out;

    detect_mask_kernel<<<1, 1>>>(mraw);
    norm_mask_kernel<<<NRAYS / 256, 256>>>(mraw);

    feature_kernel<<<NRAYS / 8, 256>>>(orig, vec, t1, t2, nmin, nmax, feats, idxs);

    dim3 ggrid(DIM / BN, NRAYS / BM);   // (4, 512)
    gemm_kernel<<<ggrid, 256>>>(0, W0, b0);

    for (int i = 0; i < NLAYERS; i++) {
        prep_kernel<<<NRAYS / 8, 256>>>(gl + i * DIM, betal + i * DIM);
        gemm_kernel<<<ggrid, 256>>>(1, Wl + (size_t)i * DIM * DIM, bl + i * DIM);
    }

    head_kernel<<<NRAYS / 8, 256>>>(Wcls, bcls, Wdist, bdist, t1, din, out);
}

// round 16
// speedup vs baseline: 1.8889x; 1.8889x over previous
#include <cuda_runtime.h>

#define NRAYS 65536
#define NPTS 32
#define FEATD 128
#define DIM 512
#define NLAYERS 6
#define KG 512    /* unified GEMM K: 4*FEATD == DIM */

#define BM 128
#define BN 128
#define BK 8

// Scratch (allocation-free rule: __device__ globals)
__device__ float g_G[(size_t)NRAYS * KG];    // 128 MB poly-compressed features
__device__ float g_h[(size_t)NRAYS * DIM];   // GEMM output
__device__ float g_y[(size_t)NRAYS * DIM];   // relu+LN output
__device__ float g_M[DIM * KG];              // compressed W0
__device__ float g_len[NRAYS];
__device__ unsigned char g_mask[NRAYS];      // normalized mask
__device__ int g_mask_kind;                  // 0=u8, 1=i32, 2=f32

// ---------- packed f32x2 helpers (FFMA2) ----------
static __device__ __forceinline__ unsigned long long pk2(float x, float y) {
    unsigned long long r;
    asm("mov.b64 %0, {%1, %2};" : "=l"(r) : "f"(x), "f"(y));
    return r;
}
static __device__ __forceinline__ unsigned long long ff2(unsigned long long a,
                                                         unsigned long long b,
                                                         unsigned long long c) {
    unsigned long long d;
    asm("fma.rn.f32x2 %0, %1, %2, %3;" : "=l"(d) : "l"(a), "l"(b), "l"(c));
    return d;
}
static __device__ __forceinline__ void upk2(unsigned long long v, float& x, float& y) {
    asm("mov.b64 {%0, %1}, %2;" : "=f"(x), "=f"(y) : "l"(v));
}

// ---------------------------------------------------------------------------
// Mask dtype detection + normalization (deterministic insurance).
// ---------------------------------------------------------------------------
__global__ void detect_mask_kernel(const unsigned char* __restrict__ mraw)
{
    int c1 = 0;
    for (int i = 0; i < 512; i++) c1 += (mraw[i] == 1);
    int kind;
    if (c1 > 256)     kind = 0;   // u8
    else if (c1 > 25) kind = 1;   // i32
    else              kind = 2;   // f32
    g_mask_kind = kind;
}

__global__ void norm_mask_kernel(const unsigned char* __restrict__ mraw)
{
    int r = blockIdx.x * blockDim.x + threadIdx.x;
    if (r >= NRAYS) return;
    int kind = g_mask_kind;
    bool m;
    if (kind == 0)      m = (mraw[r] != 0);
    else if (kind == 1) m = (((const int*)mraw)[r] != 0);
    else                m = (((const float*)mraw)[r] != 0.0f);
    g_mask[r] = m ? 1 : 0;
}

// ---------------------------------------------------------------------------
// Kernel M: compress W0 [512,4096] -> M [512,512]:
//   M[o, j*128+f] = sum_p W0[o, p*128+f] * (p/31)^j
// One thread per output element; adjacent threads -> adjacent f (coalesced).
// ---------------------------------------------------------------------------
__global__ void build_M_kernel(const float* __restrict__ W0)
{
    int gid = blockIdx.x * blockDim.x + threadIdx.x;
    if (gid >= DIM * KG) return;
    int o   = gid >> 9;          // /512
    int col = gid & 511;
    int j   = col >> 7;          // 0..3
    int f   = col & 127;

    const float* w = W0 + (size_t)o * 4096 + f;
    float s = 0.f;
    #pragma unroll 8
    for (int p = 0; p < NPTS; p++) {
        float t = (float)p * (1.0f / 31.0f);
        float tj = 1.f;
        for (int q = 0; q < 4; q++) { if (q == j) break; tj *= t; }
        // tj = t^j computed branch-lite:
        // (the loop above multiplies j times)
        s = fmaf(w[p * FEATD], tj, s);
    }
    g_M[gid] = s;
}

// ---------------------------------------------------------------------------
// Kernel G: per-ray cubic-poly feature compression -> g_G [NRAYS, 512], g_len
// One warp per ray; each lane owns 4 consecutive features.
//   G[r, j*128+f] = sum_c coef_j(c) * feat_c[f],  w_c(t) = sum_j coef_j t^j
// ---------------------------------------------------------------------------
__global__ void g_kernel(const float* __restrict__ orig,
                         const float* __restrict__ vec,
                         const float* __restrict__ t1g,
                         const float* __restrict__ t2g,
                         const float* __restrict__ nming,
                         const float* __restrict__ nmaxg,
                         const float* __restrict__ feats,
                         const int*   __restrict__ idxs)
{
    int r = (blockIdx.x * blockDim.x + threadIdx.x) >> 5;
    int lane = threadIdx.x & 31;
    if (r >= NRAYS) return;

    int idx = g_mask[r] ? idxs[r] : 0;
    float a1 = t1g[r], a2 = t2g[r];
    float ox = orig[3*r+0], oy = orig[3*r+1], oz = orig[3*r+2];
    float vx = vec[3*r+0],  vy = vec[3*r+1],  vz = vec[3*r+2];

    float iox = fmaf(vx, a1, ox), ioy = fmaf(vy, a1, oy), ioz = fmaf(vz, a1, oz);
    float dt  = a2 - a1;
    float ivx = vx * dt, ivy = vy * dt, ivz = vz * dt;
    float iex = iox + ivx, iey = ioy + ivy, iez = ioz + ivz;

    float nx = nming[3*idx+0], ny = nming[3*idx+1], nz = nming[3*idx+2];
    float sx = nmaxg[3*idx+0] - nx;
    float sy = nmaxg[3*idx+1] - ny;
    float sz = nmaxg[3*idx+2] - nz;

    float o0 = fminf(fmaxf((iox - nx) / sx, 0.f), 1.f);
    float o1 = fminf(fmaxf((ioy - ny) / sy, 0.f), 1.f);
    float o2 = fminf(fmaxf((ioz - nz) / sz, 0.f), 1.f);
    float e0 = fminf(fmaxf((iex - nx) / sx, 0.f), 1.f);
    float e1 = fminf(fmaxf((iey - ny) / sy, 0.f), 1.f);
    float e2 = fminf(fmaxf((iez - nz) / sz, 0.f), 1.f);

    if (lane == 0)
        g_len[r] = sqrtf(ivx*ivx + ivy*ivy + ivz*ivz);

    float d0 = e0 - o0, d1 = e1 - o1, d2 = e2 - o2;

    // per-axis linear terms: bit=0 -> (1-o, -d); bit=1 -> (o, d)
    float xa[2] = {1.f - o0, o0}, xb[2] = {-d0, d0};
    float ya[2] = {1.f - o1, o1}, yb[2] = {-d1, d1};
    float za[2] = {1.f - o2, o2}, zb[2] = {-d2, d2};

    // corner bit patterns in feature order: 000,100,010,001,101,011,110,111
    const int BX[8] = {0,1,0,0,1,0,1,1};
    const int BY[8] = {0,0,1,0,0,1,1,1};
    const int BZ[8] = {0,0,0,1,1,1,0,1};

    const float4* fb = (const float4*)(feats + (size_t)idx * 1024);

    float4 g0 = make_float4(0,0,0,0), g1 = g0, g2 = g0, g3 = g0;

    #pragma unroll
    for (int c = 0; c < 8; c++) {
        float A1 = xa[BX[c]], B1 = xb[BX[c]];
        float A2 = ya[BY[c]], B2 = yb[BY[c]];
        float A3 = za[BZ[c]], B3 = zb[BZ[c]];
        // (A1+B1 t)(A2+B2 t)(A3+B3 t) expanded:
        float c0 = A1*A2*A3;
        float c1 = A1*A2*B3 + A1*B2*A3 + B1*A2*A3;
        float c2 = A1*B2*B3 + B1*A2*B3 + B1*B2*A3;
        float c3 = B1*B2*B3;

        float4 f = fb[c * 32 + lane];
        g0.x = fmaf(c0, f.x, g0.x); g0.y = fmaf(c0, f.y, g0.y);
        g0.z = fmaf(c0, f.z, g0.z); g0.w = fmaf(c0, f.w, g0.w);
        g1.x = fmaf(c1, f.x, g1.x); g1.y = fmaf(c1, f.y, g1.y);
        g1.z = fmaf(c1, f.z, g1.z); g1.w = fmaf(c1, f.w, g1.w);
        g2.x = fmaf(c2, f.x, g2.x); g2.y = fmaf(c2, f.y, g2.y);
        g2.z = fmaf(c2, f.z, g2.z); g2.w = fmaf(c2, f.w, g2.w);
        g3.x = fmaf(c3, f.x, g3.x); g3.y = fmaf(c3, f.y, g3.y);
        g3.z = fmaf(c3, f.z, g3.z); g3.w = fmaf(c3, f.w, g3.w);
    }

    float4* Go = (float4*)(g_G + (size_t)r * KG) + lane;
    Go[0]  = g0;   // j=0 : cols [0,128)
    Go[32] = g1;   // j=1 : cols [128,256)
    Go[64] = g2;   // j=2 : cols [256,384)
    Go[96] = g3;   // j=3 : cols [384,512)
}

// ---------------------------------------------------------------------------
// Kernel 2: C[M,512] = A[M,512] * B^T + bias, fp32 via packed FFMA2.
// K = 512 compile-time. Double-buffered smem, 128x128x8, 8x8/thread, 256 thr.
// ---------------------------------------------------------------------------
__global__ __launch_bounds__(256, 2)
void gemm_kernel(const float* __restrict__ A, const float* __restrict__ B,
                 const float* __restrict__ bias)
{
    float* __restrict__ C = g_h;

    __shared__ __align__(16) float As[2][BK][BM];
    __shared__ __align__(16) float Bs[2][BK][BN];

    const int tid = threadIdx.x;
    const int bm = blockIdx.y * BM;
    const int bn = blockIdx.x * BN;

    const float* Ap = A + (size_t)(bm + (tid >> 1)) * KG + (tid & 1) * 4;
    const float* Bp = B + (size_t)(bn + (tid >> 1)) * KG + (tid & 1) * 4;
    const int srow = (tid & 1) * 4;
    const int scol = tid >> 1;

    {
        float4 av = *(const float4*)Ap;
        float4 bv = *(const float4*)Bp;
        As[0][srow+0][scol] = av.x; As[0][srow+1][scol] = av.y;
        As[0][srow+2][scol] = av.z; As[0][srow+3][scol] = av.w;
        Bs[0][srow+0][scol] = bv.x; Bs[0][srow+1][scol] = bv.y;
        Bs[0][srow+2][scol] = bv.z; Bs[0][srow+3][scol] = bv.w;
    }
    __syncthreads();

    const int tx = tid & 15;
    const int ty = tid >> 4;

    unsigned long long acc[8][4];
    #pragma unroll
    for (int i = 0; i < 8; i++)
        #pragma unroll
        for (int j = 0; j < 4; j++)
            acc[i][j] = 0ull;

    const int ktiles = KG / BK;    // 64
    int buf = 0;
    for (int kt = 0; kt < ktiles; kt++) {
        float4 an, bnv;
        const bool pf = (kt + 1 < ktiles);
        if (pf) {
            an  = *(const float4*)(Ap + (kt + 1) * BK);
            bnv = *(const float4*)(Bp + (kt + 1) * BK);
        }
        float (*Ac)[BM] = As[buf];
        float (*Bc)[BN] = Bs[buf];
        #pragma unroll
        for (int kk = 0; kk < BK; kk++) {
            float4 a0 = *(const float4*)&Ac[kk][ty * 8];
            float4 a1 = *(const float4*)&Ac[kk][ty * 8 + 4];
            const unsigned long long* bp = (const unsigned long long*)&Bc[kk][tx * 8];
            unsigned long long b0 = bp[0], b1 = bp[1], b2 = bp[2], b3 = bp[3];
            float a[8] = {a0.x, a0.y, a0.z, a0.w, a1.x, a1.y, a1.z, a1.w};
            #pragma unroll
            for (int i = 0; i < 8; i++) {
                unsigned long long aa = pk2(a[i], a[i]);
                acc[i][0] = ff2(aa, b0, acc[i][0]);
                acc[i][1] = ff2(aa, b1, acc[i][1]);
                acc[i][2] = ff2(aa, b2, acc[i][2]);
                acc[i][3] = ff2(aa, b3, acc[i][3]);
            }
        }
        if (pf) {
            float (*An_)[BM] = As[buf ^ 1];
            float (*Bn_)[BN] = Bs[buf ^ 1];
            An_[srow+0][scol] = an.x;  An_[srow+1][scol] = an.y;
            An_[srow+2][scol] = an.z;  An_[srow+3][scol] = an.w;
            Bn_[srow+0][scol] = bnv.x; Bn_[srow+1][scol] = bnv.y;
            Bn_[srow+2][scol] = bnv.z; Bn_[srow+3][scol] = bnv.w;
        }
        __syncthreads();
        buf ^= 1;
    }

    float4 bb0 = *(const float4*)(bias + bn + tx * 8);
    float4 bb1 = *(const float4*)(bias + bn + tx * 8 + 4);
    #pragma unroll
    for (int i = 0; i < 8; i++) {
        float o0, o1, o2, o3, o4, o5, o6, o7;
        upk2(acc[i][0], o0, o1);
        upk2(acc[i][1], o2, o3);
        upk2(acc[i][2], o4, o5);
        upk2(acc[i][3], o6, o7);
        float4 r0 = make_float4(o0 + bb0.x, o1 + bb0.y, o2 + bb0.z, o3 + bb0.w);
        float4 r1 = make_float4(o4 + bb1.x, o5 + bb1.y, o6 + bb1.z, o7 + bb1.w);
        float* crow = C + (size_t)(bm + ty * 8 + i) * DIM + bn + tx * 8;
        *(float4*)crow       = r0;
        *(float4*)(crow + 4) = r1;
    }
}

// ---------------------------------------------------------------------------
// Kernel 3: y = gamma * LN(relu(h)) + beta     (warp per row)
// ---------------------------------------------------------------------------
__global__ void prep_kernel(const float* __restrict__ gamma, const float* __restrict__ beta)
{
    int r = (blockIdx.x * blockDim.x + threadIdx.x) >> 5;
    int lane = threadIdx.x & 31;
    if (r >= NRAYS) return;

    const float4* hp = (const float4*)(g_h + (size_t)r * DIM);
    float4 v[4];
    float s = 0.f, s2 = 0.f;
    #pragma unroll
    for (int q = 0; q < 4; q++) {
        float4 t = hp[q * 32 + lane];
        t.x = fmaxf(t.x, 0.f); t.y = fmaxf(t.y, 0.f);
        t.z = fmaxf(t.z, 0.f); t.w = fmaxf(t.w, 0.f);
        v[q] = t;
        s  += t.x + t.y + t.z + t.w;
        s2 += t.x*t.x + t.y*t.y + t.z*t.z + t.w*t.w;
    }
    #pragma unroll
    for (int o = 16; o; o >>= 1) {
        s  += __shfl_xor_sync(0xffffffffu, s,  o);
        s2 += __shfl_xor_sync(0xffffffffu, s2, o);
    }
    float mu   = s * (1.0f / DIM);
    float var  = fmaf(-mu, mu, s2 * (1.0f / DIM));
    float rstd = rsqrtf(var + 1e-5f);

    float4* yp = (float4*)(g_y + (size_t)r * DIM);
    #pragma unroll
    for (int q = 0; q < 4; q++) {
        int c0 = q * 128 + lane * 4;
        float4 g4 = *(const float4*)(gamma + c0);
        float4 b4 = *(const float4*)(beta + c0);
        float4 o4;
        o4.x = fmaf((v[q].x - mu) * rstd, g4.x, b4.x);
        o4.y = fmaf((v[q].y - mu) * rstd, g4.y, b4.y);
        o4.z = fmaf((v[q].z - mu) * rstd, g4.z, b4.z);
        o4.w = fmaf((v[q].w - mu) * rstd, g4.w, b4.w);
        yp[q * 32 + lane] = o4;
    }
}

// ---------------------------------------------------------------------------
// Kernel 4: heads + mask logic -> out[2, NRAYS]
// ---------------------------------------------------------------------------
__global__ void head_kernel(const float* __restrict__ Wcls, const float* __restrict__ bcls,
                            const float* __restrict__ Wdist, const float* __restrict__ bdist,
                            const float* __restrict__ t1g, const float* __restrict__ din,
                            float* __restrict__ out)
{
    int r = (blockIdx.x * blockDim.x + threadIdx.x) >> 5;
    int lane = threadIdx.x & 31;
    if (r >= NRAYS) return;

    const float4* hp = (const float4*)(g_h + (size_t)r * DIM);
    float sc = 0.f, sd = 0.f;
    #pragma unroll
    for (int q = 0; q < 4; q++) {
        float4 hv = hp[q * 32 + lane];
        hv.x = fmaxf(hv.x, 0.f); hv.y = fmaxf(hv.y, 0.f);
        hv.z = fmaxf(hv.z, 0.f); hv.w = fmaxf(hv.w, 0.f);
        int c0 = q * 128 + lane * 4;
        float4 wc = *(const float4*)(Wcls + c0);
        float4 wd = *(const float4*)(Wdist + c0);
        sc += hv.x*wc.x + hv.y*wc.y + hv.z*wc.z + hv.w*wc.w;
        sd += hv.x*wd.x + hv.y*wd.y + hv.z*wd.z + hv.w*wd.w;
    }
    #pragma unroll
    for (int o = 16; o; o >>= 1) {
        sc += __shfl_xor_sync(0xffffffffu, sc, o);
        sd += __shfl_xor_sync(0xffffffffu, sd, o);
    }
    if (lane == 0) {
        float cls  = sc + bcls[0];
        float dist = (sd + bdist[0]) * g_len[r];
        bool  m    = (g_mask[r] != 0);
        float hit  = m ? cls : 0.f;
        float dval = (m ? dist : 0.f) + t1g[r];
        float di   = din[r];
        bool  upd  = (hit > 0.f) && (dval < di) && m;
        out[r]         = hit;
        out[NRAYS + r] = upd ? dval : di;
    }
}

// ---------------------------------------------------------------------------
extern "C" void kernel_launch(void* const* d_in, const int* in_sizes, int n_in,
                              void* d_out, int out_size)
{
    const float* orig   = (const float*)d_in[0];
    const float* vec    = (const float*)d_in[1];
    const float* t1     = (const float*)d_in[2];
    const float* t2     = (const float*)d_in[3];
    const float* din    = (const float*)d_in[4];
    const float* nmin   = (const float*)d_in[5];
    const float* nmax   = (const float*)d_in[6];
    const float* feats  = (const float*)d_in[7];
    const float* W0     = (const float*)d_in[8];
    const float* b0     = (const float*)d_in[9];
    const float* Wl     = (const float*)d_in[10];
    const float* bl     = (const float*)d_in[11];
    const float* gl     = (const float*)d_in[12];
    const float* betal  = (const float*)d_in[13];
    const float* Wcls   = (const float*)d_in[14];
    const float* bcls   = (const float*)d_in[15];
    const float* Wdist  = (const float*)d_in[16];
    const float* bdist  = (const float*)d_in[17];
    const int*   idxs   = (const int*)d_in[18];
    const unsigned char* mraw = (const unsigned char*)d_in[19];
    float* out = (float*)d_out;

    detect_mask_kernel<<<1, 1>>>(mraw);
    norm_mask_kernel<<<NRAYS / 256, 256>>>(mraw);

    build_M_kernel<<<(DIM * KG) / 256, 256>>>(W0);
    g_kernel<<<NRAYS / 8, 256>>>(orig, vec, t1, t2, nmin, nmax, feats, idxs);

    dim3 ggrid(DIM / BN, NRAYS / BM);   // (4, 512)
    // layer 0 via compressed M
    { const float* Gp = nullptr; (void)Gp; }
    {
        float* Ga; cudaGetSymbolAddress((void**)&Ga, g_G);
        float* Ma; cudaGetSymbolAddress((void**)&Ma, g_M);
        float* Ya; cudaGetSymbolAddress((void**)&Ya, g_y);
        gemm_kernel<<<ggrid, 256>>>(Ga, Ma, b0);
        for (int i = 0; i < NLAYERS; i++) {
            prep_kernel<<<NRAYS / 8, 256>>>(gl + i * DIM, betal + i * DIM);
            gemm_kernel<<<ggrid, 256>>>(Ya, Wl + (size_t)i * DIM * DIM, bl + i * DIM);
        }
    }

    head_kernel<<<NRAYS / 8, 256>>>(Wcls, bcls, Wdist, bdist, t1, din, out);
}